// round 2
// baseline (speedup 1.0000x reference)
#include <cuda_runtime.h>
#include <cstdint>
#include <cstddef>

#define TSIZE (1u << 18)
#define TMASK (TSIZE - 1u)
#define NLEV 16
#define P1 2654435761u
#define P2 805459861u

// Feature-interleaved scratch (device globals: no allocation).
__device__ float2 g_hash[15u * TSIZE];    // hashed levels 3..15 use l-1 = 2..14
__device__ float2 g_dense[16 * 16 * 16];  // level 0 (dense input grid)
__device__ float2 g_grid1[20 * 20 * 20];  // level 1 materialized dense (res 20)
__device__ float2 g_grid2[25 * 25 * 25];  // level 2 materialized dense (res 25)

// smem layout: [0,4096) dense16 | [4096,12096) grid20 | [12096,27721) grid25
#define SM_DENSE 0
#define SM_G1 4096
#define SM_G2 12096
#define SM_F2_TOTAL 27721
#define SM_BYTES (SM_F2_TOTAL * 8)  // 221768 B

// ---------------------------------------------------------------------------
// Repack + materialize coarse dense grids.
// ---------------------------------------------------------------------------
__global__ void repack_kernel(const float* __restrict__ dense,
                              const float* __restrict__ hash) {
    unsigned i = blockIdx.x * blockDim.x + threadIdx.x;
    if (i < 15u * TSIZE) {
        unsigned l = i >> 18;
        unsigned t = i & TMASK;
        const float* base = hash + (size_t)l * (2u * TSIZE);
        g_hash[i] = make_float2(base[t], base[TSIZE + t]);
    }
    if (i < 4096u) {
        g_dense[i] = make_float2(dense[i], dense[4096u + i]);
    }
    if (i < 8000u) {  // level 1, res 20, hash table index 0
        unsigned x = i / 400u, y = (i / 20u) % 20u, z = i % 20u;
        unsigned h = (x ^ (y * P1) ^ (z * P2)) & TMASK;
        const float* base = hash;  // level index 0
        g_grid1[i] = make_float2(base[h], base[TSIZE + h]);
    }
    if (i < 15625u) {  // level 2, res 25, hash table index 1
        unsigned x = i / 625u, y = (i / 25u) % 25u, z = i % 25u;
        unsigned h = (x ^ (y * P1) ^ (z * P2)) & TMASK;
        const float* base = hash + (size_t)(2u * TSIZE);  // level index 1
        g_grid2[i] = make_float2(base[h], base[TSIZE + h]);
    }
}

// ---------------------------------------------------------------------------
// Persistent encode kernel: coarse levels 0-2 from smem, levels 3-15 via L2.
// ---------------------------------------------------------------------------
__global__ __launch_bounds__(1024, 1)
void encode_kernel(const float* __restrict__ coords,
                   float* __restrict__ out, int N) {
    extern __shared__ float2 smem[];

    // Cooperative smem fill (coalesced float2 copies), once per CTA.
    for (int j = threadIdx.x; j < 4096; j += blockDim.x)
        smem[SM_DENSE + j] = g_dense[j];
    for (int j = threadIdx.x; j < 8000; j += blockDim.x)
        smem[SM_G1 + j] = g_grid1[j];
    for (int j = threadIdx.x; j < 15625; j += blockDim.x)
        smem[SM_G2 + j] = g_grid2[j];
    __syncthreads();

    constexpr int RES[NLEV] = {16, 20, 25, 32, 40, 50, 64, 80,
                               101, 128, 161, 203, 256, 322, 406, 512};

    const int stride = gridDim.x * blockDim.x;
    for (int i = blockIdx.x * blockDim.x + threadIdx.x; i < N; i += stride) {
        const float cx = __ldg(&coords[3 * i + 0]);
        const float cy = __ldg(&coords[3 * i + 1]);
        const float cz = __ldg(&coords[3 * i + 2]);

        float4* __restrict__ out4 = reinterpret_cast<float4*>(out + (size_t)i * 32);
        float4 obuf = make_float4(0.f, 0.f, 0.f, 0.f);

#pragma unroll
        for (int l = 0; l < NLEV; ++l) {
            const int res = RES[l];
            const float rm1 = (float)(res - 1);

            float px = fminf(fmaxf((cx + 1.0f) * 0.5f * rm1, 0.0f), rm1);
            float py = fminf(fmaxf((cy + 1.0f) * 0.5f * rm1, 0.0f), rm1);
            float pz = fminf(fmaxf((cz + 1.0f) * 0.5f * rm1, 0.0f), rm1);

            int ix0 = (int)px;  float wx = px - (float)ix0;
            int iy0 = (int)py;  float wy = py - (float)iy0;
            int iz0 = (int)pz;  float wz = pz - (float)iz0;
            int ix1 = min(ix0 + 1, res - 1);
            int iy1 = min(iy0 + 1, res - 1);
            int iz1 = min(iz0 + 1, res - 1);

            const float wxv0 = 1.0f - wx, wxv1 = wx;
            const float wyv0 = 1.0f - wy, wyv1 = wy;
            const float wzv0 = 1.0f - wz, wzv1 = wz;

            float2 f[8];
            float  wg[8];

            if (l < 3) {
                // Coarse levels: dense grid in shared memory (no l1tex).
                const float2* __restrict__ tb =
                    (l == 0) ? (smem + SM_DENSE) :
                    (l == 1) ? (smem + SM_G1) : (smem + SM_G2);
#pragma unroll
                for (int c = 0; c < 8; ++c) {
                    const int xi = (c & 4) ? ix1 : ix0;
                    const int yi = (c & 2) ? iy1 : iy0;
                    const int zi = (c & 1) ? iz1 : iz0;
                    f[c] = tb[(xi * res + yi) * res + zi];
                    wg[c] = ((c & 4) ? wxv1 : wxv0) *
                            ((c & 2) ? wyv1 : wyv0) *
                            ((c & 1) ? wzv1 : wzv0);
                }
            } else {
                const float2* __restrict__ tbl = g_hash + (size_t)(l - 1) * TSIZE;
                const unsigned hx0 = (unsigned)ix0;  // prime 1
                const unsigned hx1 = (unsigned)ix1;
                const unsigned hy0 = (unsigned)iy0 * P1;
                const unsigned hy1 = (unsigned)iy1 * P1;
                const unsigned hz0 = (unsigned)iz0 * P2;
                const unsigned hz1 = (unsigned)iz1 * P2;
#pragma unroll
                for (int c = 0; c < 8; ++c) {
                    const unsigned h = (((c & 4) ? hx1 : hx0) ^
                                        ((c & 2) ? hy1 : hy0) ^
                                        ((c & 1) ? hz1 : hz0)) & TMASK;
                    f[c] = __ldg(&tbl[h]);
                    wg[c] = ((c & 4) ? wxv1 : wxv0) *
                            ((c & 2) ? wyv1 : wyv0) *
                            ((c & 1) ? wzv1 : wzv0);
                }
            }

            float a0 = 0.0f, a1 = 0.0f;
#pragma unroll
            for (int c = 0; c < 8; ++c) {
                a0 = fmaf(f[c].x, wg[c], a0);
                a1 = fmaf(f[c].y, wg[c], a1);
            }

            if ((l & 1) == 0) {
                obuf.x = a0; obuf.y = a1;
            } else {
                obuf.z = a0; obuf.w = a1;
                out4[l >> 1] = obuf;
            }
        }
    }
}

// ---------------------------------------------------------------------------
// kernel_launch
// ---------------------------------------------------------------------------
extern "C" void kernel_launch(void* const* d_in, const int* in_sizes, int n_in,
                              void* d_out, int out_size) {
    const float* coords = (const float*)d_in[0];
    const float* dense  = (const float*)d_in[1];
    const float* hash   = (const float*)d_in[2];
    float* out = (float*)d_out;

    const int N = in_sizes[0] / 3;

    const unsigned repack_total = 15u * TSIZE;
    repack_kernel<<<(repack_total + 255u) / 256u, 256>>>(dense, hash);

    int num_sms = 148;
    cudaDeviceGetAttribute(&num_sms, cudaDevAttrMultiProcessorCount, 0);

    cudaFuncSetAttribute(encode_kernel,
                         cudaFuncAttributeMaxDynamicSharedMemorySize, SM_BYTES);
    encode_kernel<<<num_sms, 1024, SM_BYTES>>>(coords, out, N);
}

// round 3
// speedup vs baseline: 3.1852x; 3.1852x over previous
#include <cuda_runtime.h>
#include <cstdint>
#include <cstddef>

#define TSIZE (1u << 18)
#define TMASK (TSIZE - 1u)
#define NLEV 16
#define P1 2654435761u
#define P2 805459861u

#define NBUCK 32768   // 32^3 buckets
#define NMAX (1 << 21)

// Device-global scratch (no allocation).
__device__ float2   g_hash[15u * TSIZE];   // feature-interleaved hash tables
__device__ float2   g_dense[16 * 16 * 16];
__device__ unsigned g_count[NBUCK];
__device__ unsigned g_cursor[NBUCK];
__device__ float4   g_buf[NMAX];           // bucketed points {x,y,z,idx}

// ---------------------------------------------------------------------------
// Repack tables to float2 + zero histogram.
// ---------------------------------------------------------------------------
__global__ void repack_kernel(const float* __restrict__ dense,
                              const float* __restrict__ hash) {
    unsigned i = blockIdx.x * blockDim.x + threadIdx.x;
    if (i < 15u * TSIZE) {
        unsigned l = i >> 18;
        unsigned t = i & TMASK;
        const float* base = hash + (size_t)l * (2u * TSIZE);
        g_hash[i] = make_float2(base[t], base[TSIZE + t]);
    }
    if (i < 4096u)
        g_dense[i] = make_float2(dense[i], dense[4096u + i]);
    if (i < NBUCK)
        g_count[i] = 0u;
}

__device__ __forceinline__ int bucket_of(float cx, float cy, float cz) {
    int bx = min(31, max(0, (int)((cx + 1.0f) * 16.0f)));
    int by = min(31, max(0, (int)((cy + 1.0f) * 16.0f)));
    int bz = min(31, max(0, (int)((cz + 1.0f) * 16.0f)));
    return (bx * 32 + by) * 32 + bz;
}

__global__ void hist_kernel(const float* __restrict__ coords, int N) {
    int i = blockIdx.x * blockDim.x + threadIdx.x;
    if (i >= N) return;
    int b = bucket_of(coords[3 * i], coords[3 * i + 1], coords[3 * i + 2]);
    atomicAdd(&g_count[b], 1u);
}

// Single-block exclusive scan over 32768 counters -> g_cursor.
__global__ __launch_bounds__(1024)
void scan_kernel() {
    __shared__ unsigned part[1024];
    const int t = threadIdx.x;
    const unsigned base = (unsigned)t * 32u;
    unsigned local[32];
    unsigned s = 0;
#pragma unroll
    for (int j = 0; j < 32; ++j) { local[j] = s; s += g_count[base + j]; }
    part[t] = s;
    __syncthreads();
    for (int off = 1; off < 1024; off <<= 1) {
        unsigned v = 0;
        if (t >= off) v = part[t - off];
        __syncthreads();
        if (t >= off) part[t] += v;
        __syncthreads();
    }
    const unsigned pre = (t == 0) ? 0u : part[t - 1];
#pragma unroll
    for (int j = 0; j < 32; ++j) g_cursor[base + j] = pre + local[j];
}

__global__ void scatter_kernel(const float* __restrict__ coords, int N) {
    int i = blockIdx.x * blockDim.x + threadIdx.x;
    if (i >= N) return;
    float x = coords[3 * i], y = coords[3 * i + 1], z = coords[3 * i + 2];
    int b = bucket_of(x, y, z);
    unsigned slot = atomicAdd(&g_cursor[b], 1u);
    g_buf[slot] = make_float4(x, y, z, __int_as_float(i));
}

// ---------------------------------------------------------------------------
// Encode: Round-1 structure (256 thr, high occupancy), bucketed point order.
// ---------------------------------------------------------------------------
__global__ __launch_bounds__(256)
void encode_kernel(float* __restrict__ out, int N) {
    int i = blockIdx.x * blockDim.x + threadIdx.x;
    if (i >= N) return;

    const float4 pt = g_buf[i];
    const float cx = pt.x, cy = pt.y, cz = pt.z;
    const int idx = __float_as_int(pt.w);

    float4* __restrict__ out4 = reinterpret_cast<float4*>(out + (size_t)idx * 32);

    constexpr int RES[NLEV] = {16, 20, 25, 32, 40, 50, 64, 80,
                               101, 128, 161, 203, 256, 322, 406, 512};

    float4 obuf = make_float4(0.f, 0.f, 0.f, 0.f);

#pragma unroll
    for (int l = 0; l < NLEV; ++l) {
        const int res = RES[l];
        const float rm1 = (float)(res - 1);

        float px = fminf(fmaxf((cx + 1.0f) * 0.5f * rm1, 0.0f), rm1);
        float py = fminf(fmaxf((cy + 1.0f) * 0.5f * rm1, 0.0f), rm1);
        float pz = fminf(fmaxf((cz + 1.0f) * 0.5f * rm1, 0.0f), rm1);

        int ix0 = (int)px;  float wx = px - (float)ix0;
        int iy0 = (int)py;  float wy = py - (float)iy0;
        int iz0 = (int)pz;  float wz = pz - (float)iz0;
        int ix1 = min(ix0 + 1, res - 1);
        int iy1 = min(iy0 + 1, res - 1);
        int iz1 = min(iz0 + 1, res - 1);

        const float wxv0 = 1.0f - wx, wxv1 = wx;
        const float wyv0 = 1.0f - wy, wyv1 = wy;
        const float wzv0 = 1.0f - wz, wzv1 = wz;

        float2 f[8];
        float  wg[8];

        if (l == 0) {
#pragma unroll
            for (int c = 0; c < 8; ++c) {
                const int xi = (c & 4) ? ix1 : ix0;
                const int yi = (c & 2) ? iy1 : iy0;
                const int zi = (c & 1) ? iz1 : iz0;
                f[c] = __ldg(&g_dense[(xi * 16 + yi) * 16 + zi]);
                wg[c] = ((c & 4) ? wxv1 : wxv0) *
                        ((c & 2) ? wyv1 : wyv0) *
                        ((c & 1) ? wzv1 : wzv0);
            }
        } else {
            const float2* __restrict__ tbl = g_hash + (size_t)(l - 1) * TSIZE;
            const unsigned hx0 = (unsigned)ix0;  // prime 1
            const unsigned hx1 = (unsigned)ix1;
            const unsigned hy0 = (unsigned)iy0 * P1;
            const unsigned hy1 = (unsigned)iy1 * P1;
            const unsigned hz0 = (unsigned)iz0 * P2;
            const unsigned hz1 = (unsigned)iz1 * P2;
#pragma unroll
            for (int c = 0; c < 8; ++c) {
                const unsigned h = (((c & 4) ? hx1 : hx0) ^
                                    ((c & 2) ? hy1 : hy0) ^
                                    ((c & 1) ? hz1 : hz0)) & TMASK;
                f[c] = __ldg(&tbl[h]);
                wg[c] = ((c & 4) ? wxv1 : wxv0) *
                        ((c & 2) ? wyv1 : wyv0) *
                        ((c & 1) ? wzv1 : wzv0);
            }
        }

        float a0 = 0.0f, a1 = 0.0f;
#pragma unroll
        for (int c = 0; c < 8; ++c) {
            a0 = fmaf(f[c].x, wg[c], a0);
            a1 = fmaf(f[c].y, wg[c], a1);
        }

        if ((l & 1) == 0) {
            obuf.x = a0; obuf.y = a1;
        } else {
            obuf.z = a0; obuf.w = a1;
            out4[l >> 1] = obuf;
        }
    }
}

// ---------------------------------------------------------------------------
// kernel_launch: repack -> hist -> scan -> scatter -> encode
// ---------------------------------------------------------------------------
extern "C" void kernel_launch(void* const* d_in, const int* in_sizes, int n_in,
                              void* d_out, int out_size) {
    const float* coords = (const float*)d_in[0];
    const float* dense  = (const float*)d_in[1];
    const float* hash   = (const float*)d_in[2];
    float* out = (float*)d_out;

    const int N = in_sizes[0] / 3;
    const int nb = (N + 255) / 256;

    const unsigned repack_total = 15u * TSIZE;
    repack_kernel<<<(repack_total + 255u) / 256u, 256>>>(dense, hash);
    hist_kernel<<<nb, 256>>>(coords, N);
    scan_kernel<<<1, 1024>>>();
    scatter_kernel<<<nb, 256>>>(coords, N);
    encode_kernel<<<nb, 256>>>(out, N);
}